// round 2
// baseline (speedup 1.0000x reference)
#include <cuda_runtime.h>
#include <cuda_bf16.h>

// Problem constants (fixed shapes from reference setup_inputs)
#define NN0 50000
#define NN1 10000
#define NN2 2048
#define DIN 256
#define DHID 1000
#define NCLS 5000
#define EE0 500000
#define EE1 100000

// ---------------- device scratch (static, allocation-free) ----------------
__device__ int   g_cnt_out0[NN0];
__device__ int   g_cnt_in0[NN1];
__device__ int   g_cnt_out1[NN1];
__device__ int   g_cnt_in1[NN2];
__device__ float g_rs_out0[NN0];
__device__ float g_rs_in0[NN1];
__device__ float g_rs_out1[NN1];
__device__ float g_rs_in1[NN2];
__device__ int   g_off0[NN1 + 1];
__device__ int   g_cur0[NN1];
__device__ int   g_off1[NN2 + 1];
__device__ int   g_cur1[NN2];
__device__ int   g_srcs0[EE0];
__device__ int   g_srcs1[EE1];
__device__ float g_agg0[(size_t)NN1 * DIN];    // 10.24 MB (dst-normalized)
__device__ float g_h1s[(size_t)NN1 * DHID];    // 40 MB    (src-normalized h1)
__device__ float g_agg1[(size_t)NN2 * DHID];   // 8.2 MB   (dst-normalized)

// ---------------- setup kernels ----------------
__global__ void zero_counts_kernel() {
    int i = blockIdx.x * blockDim.x + threadIdx.x;
    int stride = gridDim.x * blockDim.x;
    for (int j = i; j < NN0; j += stride) g_cnt_out0[j] = 0;
    for (int j = i; j < NN1; j += stride) { g_cnt_in0[j] = 0; g_cnt_out1[j] = 0; }
    for (int j = i; j < NN2; j += stride) g_cnt_in1[j] = 0;
}

__global__ void degree_kernel(const int* __restrict__ s0, const int* __restrict__ d0,
                              const int* __restrict__ s1, const int* __restrict__ d1,
                              int E0, int E1) {
    int i = blockIdx.x * blockDim.x + threadIdx.x;
    int stride = gridDim.x * blockDim.x;
    for (int j = i; j < E0; j += stride) {
        atomicAdd(&g_cnt_out0[s0[j]], 1);
        atomicAdd(&g_cnt_in0[d0[j]], 1);
        if (j < E1) {
            atomicAdd(&g_cnt_out1[s1[j]], 1);
            atomicAdd(&g_cnt_in1[d1[j]], 1);
        }
    }
}

__global__ void rsqrt_kernel() {
    int i = blockIdx.x * blockDim.x + threadIdx.x;
    int stride = gridDim.x * blockDim.x;
    for (int j = i; j < NN0; j += stride)
        g_rs_out0[j] = rsqrtf((float)max(g_cnt_out0[j], 1));
    for (int j = i; j < NN1; j += stride) {
        g_rs_in0[j]  = rsqrtf((float)max(g_cnt_in0[j], 1));
        g_rs_out1[j] = rsqrtf((float)max(g_cnt_out1[j], 1));
    }
    for (int j = i; j < NN2; j += stride)
        g_rs_in1[j]  = rsqrtf((float)max(g_cnt_in1[j], 1));
}

// single-block exclusive scan over NN1 bins -> offsets + cursors (direct symbols)
__global__ void scan0_kernel() {
    __shared__ int part[1024];
    const int NB = NN1;
    const int IPT = (NB + 1023) / 1024;
    int t = threadIdx.x;
    int base = t * IPT;
    int s = 0;
    for (int i = 0; i < IPT; i++) {
        int b = base + i;
        if (b < NB) s += g_cnt_in0[b];
    }
    part[t] = s;
    __syncthreads();
    for (int d = 1; d < 1024; d <<= 1) {
        int v = (t >= d) ? part[t - d] : 0;
        __syncthreads();
        part[t] += v;
        __syncthreads();
    }
    int run = (t == 0) ? 0 : part[t - 1];
    for (int i = 0; i < IPT; i++) {
        int b = base + i;
        if (b < NB) {
            g_off0[b] = run;
            g_cur0[b] = run;
            run += g_cnt_in0[b];
        }
    }
    if (t == 1023) g_off0[NB] = run;
}

__global__ void scan1_kernel() {
    __shared__ int part[1024];
    const int NB = NN2;
    const int IPT = (NB + 1023) / 1024;
    int t = threadIdx.x;
    int base = t * IPT;
    int s = 0;
    for (int i = 0; i < IPT; i++) {
        int b = base + i;
        if (b < NB) s += g_cnt_in1[b];
    }
    part[t] = s;
    __syncthreads();
    for (int d = 1; d < 1024; d <<= 1) {
        int v = (t >= d) ? part[t - d] : 0;
        __syncthreads();
        part[t] += v;
        __syncthreads();
    }
    int run = (t == 0) ? 0 : part[t - 1];
    for (int i = 0; i < IPT; i++) {
        int b = base + i;
        if (b < NB) {
            g_off1[b] = run;
            g_cur1[b] = run;
            run += g_cnt_in1[b];
        }
    }
    if (t == 1023) g_off1[NB] = run;
}

__global__ void scatter0_kernel(const int* __restrict__ src, const int* __restrict__ dst, int E) {
    int i = blockIdx.x * blockDim.x + threadIdx.x;
    int stride = gridDim.x * blockDim.x;
    for (int j = i; j < E; j += stride) {
        int d = dst[j];
        int p = atomicAdd(&g_cur0[d], 1);
        g_srcs0[p] = src[j];
    }
}

__global__ void scatter1_kernel(const int* __restrict__ src, const int* __restrict__ dst, int E) {
    int i = blockIdx.x * blockDim.x + threadIdx.x;
    int stride = gridDim.x * blockDim.x;
    for (int j = i; j < E; j += stride) {
        int d = dst[j];
        int p = atomicAdd(&g_cur1[d], 1);
        g_srcs1[p] = src[j];
    }
}

// ---------------- layer-0 aggregation: agg0[dst] = rs_in0[dst]*sum rs_out0[s]*x[s] ----------------
// one block (64 threads) per dst row; each thread owns one float4 of 256 features
__global__ void __launch_bounds__(64) aggregate0_kernel(const float* __restrict__ x) {
    int row = blockIdx.x;
    int t = threadIdx.x;
    int beg = g_off0[row], end = g_off0[row + 1];
    const float4* x4 = (const float4*)x;
    float4 acc = make_float4(0.f, 0.f, 0.f, 0.f);
    int e = beg;
    for (; e + 1 < end; e += 2) {
        int s0 = g_srcs0[e], s1 = g_srcs0[e + 1];
        float c0 = g_rs_out0[s0], c1 = g_rs_out0[s1];
        float4 v0 = x4[(size_t)s0 * (DIN / 4) + t];
        float4 v1 = x4[(size_t)s1 * (DIN / 4) + t];
        acc.x = fmaf(v0.x, c0, acc.x); acc.y = fmaf(v0.y, c0, acc.y);
        acc.z = fmaf(v0.z, c0, acc.z); acc.w = fmaf(v0.w, c0, acc.w);
        acc.x = fmaf(v1.x, c1, acc.x); acc.y = fmaf(v1.y, c1, acc.y);
        acc.z = fmaf(v1.z, c1, acc.z); acc.w = fmaf(v1.w, c1, acc.w);
    }
    if (e < end) {
        int s0 = g_srcs0[e];
        float c0 = g_rs_out0[s0];
        float4 v0 = x4[(size_t)s0 * (DIN / 4) + t];
        acc.x = fmaf(v0.x, c0, acc.x); acc.y = fmaf(v0.y, c0, acc.y);
        acc.z = fmaf(v0.z, c0, acc.z); acc.w = fmaf(v0.w, c0, acc.w);
    }
    float sd = g_rs_in0[row];
    acc.x *= sd; acc.y *= sd; acc.z *= sd; acc.w *= sd;
    ((float4*)g_agg0)[(size_t)row * (DIN / 4) + t] = acc;
}

// ---------------- layer-1 aggregation: agg1[dst] = rs_in1[dst]*sum h1s[s] ----------------
// one block (256 threads, 250 active) per dst row; h1s already src-normalized
__global__ void __launch_bounds__(256) aggregate1_kernel() {
    int row = blockIdx.x;
    int t = threadIdx.x;
    if (t >= DHID / 4) return;
    int beg = g_off1[row], end = g_off1[row + 1];
    const float4* h4 = (const float4*)g_h1s;
    float4 acc = make_float4(0.f, 0.f, 0.f, 0.f);
    for (int e = beg; e < end; e++) {
        int s = g_srcs1[e];
        float4 v = h4[(size_t)s * (DHID / 4) + t];
        acc.x += v.x; acc.y += v.y; acc.z += v.z; acc.w += v.w;
    }
    float sd = g_rs_in1[row];
    acc.x *= sd; acc.y *= sd; acc.z *= sd; acc.w *= sd;
    ((float4*)g_agg1)[(size_t)row * (DHID / 4) + t] = acc;
}

// ---------------- SGEMM: C = epi(A @ B + bias) ----------------
// LAYER==1: A=g_agg0 [10000,256], B=W1 [256,1000], epi: (+b1)*rs_out1[row] -> g_h1s
// LAYER==2: A=g_agg1 [2048,1000], B=W2 [1000,5000], epi: sigmoid(+b2)     -> d_out
template <int LAYER>
__global__ void __launch_bounds__(256) sgemm_kernel(const float* __restrict__ B,
                                                    const float* __restrict__ bias,
                                                    float* __restrict__ Cout) {
    constexpr int M = (LAYER == 1) ? NN1 : NN2;
    constexpr int N = (LAYER == 1) ? DHID : NCLS;
    constexpr int K = (LAYER == 1) ? DIN : DHID;
    constexpr int BM = 128, BN = 128, BK = 8, TM = 8, TN = 8;

    const float* __restrict__ A = (LAYER == 1) ? g_agg0 : g_agg1;
    float* __restrict__ C = (LAYER == 1) ? g_h1s : Cout;

    __shared__ float As[BK][BM];
    __shared__ float Bs[BK][BN];

    int tid = threadIdx.x;
    int tx = tid & 15, ty = tid >> 4;
    int m0 = blockIdx.y * BM, n0 = blockIdx.x * BN;

    float acc[TM][TN];
#pragma unroll
    for (int i = 0; i < TM; i++)
#pragma unroll
        for (int j = 0; j < TN; j++) acc[i][j] = 0.f;

    int aRow = tid >> 1;             // 0..127
    int aCol = (tid & 1) * 4;        // 0,4
    int bRow = tid >> 5;             // 0..7
    int bCol = (tid & 31) * 4;       // 0..124

    for (int k0 = 0; k0 < K; k0 += BK) {
        // A tile (K % 8 == 0 for both layers)
        {
            int gm = m0 + aRow;
            float4 v = make_float4(0.f, 0.f, 0.f, 0.f);
            if (gm < M) v = *(const float4*)&A[(size_t)gm * K + k0 + aCol];
            As[aCol + 0][aRow] = v.x;
            As[aCol + 1][aRow] = v.y;
            As[aCol + 2][aRow] = v.z;
            As[aCol + 3][aRow] = v.w;
        }
        // B tile
        {
            int gn = n0 + bCol;
            float4 v = make_float4(0.f, 0.f, 0.f, 0.f);
            const float* brow = &B[(size_t)(k0 + bRow) * N];
            if (gn + 3 < N) {
                v = *(const float4*)&brow[gn];
            } else {
                float tmp[4] = {0.f, 0.f, 0.f, 0.f};
                for (int j = 0; j < 4; j++)
                    if (gn + j < N) tmp[j] = brow[gn + j];
                v = make_float4(tmp[0], tmp[1], tmp[2], tmp[3]);
            }
            *(float4*)&Bs[bRow][bCol] = v;
        }
        __syncthreads();
#pragma unroll
        for (int kk = 0; kk < BK; kk++) {
            float ra[TM], rb[TN];
#pragma unroll
            for (int i = 0; i < TM; i++) ra[i] = As[kk][ty * TM + i];
#pragma unroll
            for (int j = 0; j < TN; j++) rb[j] = Bs[kk][tx * TN + j];
#pragma unroll
            for (int i = 0; i < TM; i++)
#pragma unroll
                for (int j = 0; j < TN; j++)
                    acc[i][j] = fmaf(ra[i], rb[j], acc[i][j]);
        }
        __syncthreads();
    }

#pragma unroll
    for (int i = 0; i < TM; i++) {
        int gm = m0 + ty * TM + i;
        if (gm >= M) continue;
        float rs = (LAYER == 1) ? g_rs_out1[gm] : 1.f;
#pragma unroll
        for (int j = 0; j < TN; j++) {
            int gn = n0 + tx * TN + j;
            if (gn >= N) continue;
            float v = acc[i][j] + bias[gn];
            if (LAYER == 1) {
                v *= rs;
            } else {
                v = 1.f / (1.f + __expf(-v));
            }
            C[(size_t)gm * N + gn] = v;
        }
    }
}

// ---------------- launch ----------------
extern "C" void kernel_launch(void* const* d_in, const int* in_sizes, int n_in,
                              void* d_out, int out_size) {
    const float* x  = (const float*)d_in[0];
    const float* W1 = (const float*)d_in[1];
    const float* b1 = (const float*)d_in[2];
    const float* W2 = (const float*)d_in[3];
    const float* b2 = (const float*)d_in[4];
    const int* e0_src = (const int*)d_in[5];
    const int* e0_dst = (const int*)d_in[6];
    const int* e1_src = (const int*)d_in[7];
    const int* e1_dst = (const int*)d_in[8];
    float* out = (float*)d_out;

    int E0 = in_sizes[5];
    int E1 = in_sizes[7];

    zero_counts_kernel<<<(NN0 + 255) / 256, 256>>>();
    degree_kernel<<<1024, 256>>>(e0_src, e0_dst, e1_src, e1_dst, E0, E1);
    rsqrt_kernel<<<(NN0 + 255) / 256, 256>>>();
    scan0_kernel<<<1, 1024>>>();
    scan1_kernel<<<1, 1024>>>();
    scatter0_kernel<<<1024, 256>>>(e0_src, e0_dst, E0);
    scatter1_kernel<<<512, 256>>>(e1_src, e1_dst, E1);

    aggregate0_kernel<<<NN1, 64>>>(x);

    {
        dim3 grid((DHID + 127) / 128, (NN1 + 127) / 128);
        sgemm_kernel<1><<<grid, 256>>>(W1, b1, nullptr);
    }

    aggregate1_kernel<<<NN2, 256>>>();

    {
        dim3 grid((NCLS + 127) / 128, (NN2 + 127) / 128);
        sgemm_kernel<2><<<grid, 256>>>(W2, b2, out);
    }
}

// round 3
// speedup vs baseline: 2.2162x; 2.2162x over previous
#include <cuda_runtime.h>
#include <cuda_bf16.h>
#include <cstdint>

// Problem constants (fixed shapes from reference setup_inputs)
#define NN0 50000
#define NN1 10000
#define NN2 2048
#define DIN 256
#define DHID 1000
#define NCLS 5000
#define EE0 500000
#define EE1 100000

// ---------------- device scratch (static, allocation-free) ----------------
__device__ int   g_cnt_out0[NN0];
__device__ int   g_cnt_in0[NN1];
__device__ int   g_cnt_out1[NN1];
__device__ int   g_cnt_in1[NN2];
__device__ float g_rs_out0[NN0];
__device__ float g_rs_in0[NN1];
__device__ float g_rs_out1[NN1];
__device__ float g_rs_in1[NN2];
__device__ int   g_off0[NN1 + 1];
__device__ int   g_cur0[NN1];
__device__ int   g_off1[NN2 + 1];
__device__ int   g_cur1[NN2];
__device__ int   g_srcs0[EE0];
__device__ int   g_srcs1[EE1];
__device__ float g_agg0[(size_t)NN1 * DIN];    // dst-normalized layer0 aggregate
__device__ float g_h1s[(size_t)NN1 * DHID];    // src-normalized h1
__device__ float g_agg1[(size_t)NN2 * DHID];   // dst-normalized layer1 aggregate

// ---------------- helpers ----------------
__device__ __forceinline__ uint32_t f2tf(float x) {
    uint32_t r;
    asm("cvt.rna.tf32.f32 %0, %1;" : "=r"(r) : "f"(x));
    return r;
}

__device__ __forceinline__ void mma_tf32(float* d, const uint32_t* a, const uint32_t* b) {
    asm volatile(
        "mma.sync.aligned.m16n8k8.row.col.f32.tf32.tf32.f32 "
        "{%0,%1,%2,%3}, {%4,%5,%6,%7}, {%8,%9}, {%0,%1,%2,%3};\n"
        : "+f"(d[0]), "+f"(d[1]), "+f"(d[2]), "+f"(d[3])
        : "r"(a[0]), "r"(a[1]), "r"(a[2]), "r"(a[3]), "r"(b[0]), "r"(b[1]));
}

// ---------------- setup kernels ----------------
__global__ void zero_counts_kernel() {
    int i = blockIdx.x * blockDim.x + threadIdx.x;
    int stride = gridDim.x * blockDim.x;
    for (int j = i; j < NN0; j += stride) g_cnt_out0[j] = 0;
    for (int j = i; j < NN1; j += stride) { g_cnt_in0[j] = 0; g_cnt_out1[j] = 0; }
    for (int j = i; j < NN2; j += stride) g_cnt_in1[j] = 0;
}

__global__ void degree_kernel(const int* __restrict__ s0, const int* __restrict__ d0,
                              const int* __restrict__ s1, const int* __restrict__ d1,
                              int E0, int E1) {
    int i = blockIdx.x * blockDim.x + threadIdx.x;
    int stride = gridDim.x * blockDim.x;
    for (int j = i; j < E0; j += stride) {
        atomicAdd(&g_cnt_out0[s0[j]], 1);
        atomicAdd(&g_cnt_in0[d0[j]], 1);
        if (j < E1) {
            atomicAdd(&g_cnt_out1[s1[j]], 1);
            atomicAdd(&g_cnt_in1[d1[j]], 1);
        }
    }
}

__global__ void rsqrt_kernel() {
    int i = blockIdx.x * blockDim.x + threadIdx.x;
    int stride = gridDim.x * blockDim.x;
    for (int j = i; j < NN0; j += stride)
        g_rs_out0[j] = rsqrtf((float)max(g_cnt_out0[j], 1));
    for (int j = i; j < NN1; j += stride) {
        g_rs_in0[j]  = rsqrtf((float)max(g_cnt_in0[j], 1));
        g_rs_out1[j] = rsqrtf((float)max(g_cnt_out1[j], 1));
    }
    for (int j = i; j < NN2; j += stride)
        g_rs_in1[j]  = rsqrtf((float)max(g_cnt_in1[j], 1));
}

// hierarchical shuffle-based exclusive scan: 1024 threads, 3 barriers
__device__ __forceinline__ void scan_impl(const int* cnt, int* off, int* cur, int NB) {
    __shared__ int wsum[32];
    int t = threadIdx.x, lane = t & 31, w = t >> 5;
    int IPT = (NB + 1023) / 1024;
    int base = t * IPT;
    int loc[10];
    int s = 0;
    for (int i = 0; i < IPT; i++) {
        int b = base + i;
        int v = (b < NB) ? cnt[b] : 0;
        loc[i] = s;
        s += v;
    }
    // warp inclusive scan of per-thread totals
    int x = s;
    for (int d = 1; d < 32; d <<= 1) {
        int y = __shfl_up_sync(0xffffffffu, x, d);
        if (lane >= d) x += y;
    }
    if (lane == 31) wsum[w] = x;
    __syncthreads();
    if (w == 0) {
        int y = wsum[lane];
        int z = y;
        for (int d = 1; d < 32; d <<= 1) {
            int u = __shfl_up_sync(0xffffffffu, z, d);
            if (lane >= d) z += u;
        }
        wsum[lane] = z - y;  // exclusive warp offsets
    }
    __syncthreads();
    int excl = (x - s) + wsum[w];
    for (int i = 0; i < IPT; i++) {
        int b = base + i;
        if (b < NB) {
            int o = excl + loc[i];
            off[b] = o;
            cur[b] = o;
        }
    }
    if (t == 1023) off[NB] = excl + s;
}

__global__ void scan0_kernel() { scan_impl(g_cnt_in0, g_off0, g_cur0, NN1); }
__global__ void scan1_kernel() { scan_impl(g_cnt_in1, g_off1, g_cur1, NN2); }

__global__ void scatter0_kernel(const int* __restrict__ src, const int* __restrict__ dst, int E) {
    int i = blockIdx.x * blockDim.x + threadIdx.x;
    int stride = gridDim.x * blockDim.x;
    for (int j = i; j < E; j += stride) {
        int d = dst[j];
        int p = atomicAdd(&g_cur0[d], 1);
        g_srcs0[p] = src[j];
    }
}

__global__ void scatter1_kernel(const int* __restrict__ src, const int* __restrict__ dst, int E) {
    int i = blockIdx.x * blockDim.x + threadIdx.x;
    int stride = gridDim.x * blockDim.x;
    for (int j = i; j < E; j += stride) {
        int d = dst[j];
        int p = atomicAdd(&g_cur1[d], 1);
        g_srcs1[p] = src[j];
    }
}

// ---------------- layer-0 aggregation ----------------
__global__ void __launch_bounds__(64) aggregate0_kernel(const float* __restrict__ x) {
    int row = blockIdx.x;
    int t = threadIdx.x;
    int beg = g_off0[row], end = g_off0[row + 1];
    const float4* x4 = (const float4*)x;
    float4 acc = make_float4(0.f, 0.f, 0.f, 0.f);
    int e = beg;
    for (; e + 1 < end; e += 2) {
        int s0 = g_srcs0[e], s1 = g_srcs0[e + 1];
        float c0 = g_rs_out0[s0], c1 = g_rs_out0[s1];
        float4 v0 = x4[(size_t)s0 * (DIN / 4) + t];
        float4 v1 = x4[(size_t)s1 * (DIN / 4) + t];
        acc.x = fmaf(v0.x, c0, acc.x); acc.y = fmaf(v0.y, c0, acc.y);
        acc.z = fmaf(v0.z, c0, acc.z); acc.w = fmaf(v0.w, c0, acc.w);
        acc.x = fmaf(v1.x, c1, acc.x); acc.y = fmaf(v1.y, c1, acc.y);
        acc.z = fmaf(v1.z, c1, acc.z); acc.w = fmaf(v1.w, c1, acc.w);
    }
    if (e < end) {
        int s0 = g_srcs0[e];
        float c0 = g_rs_out0[s0];
        float4 v0 = x4[(size_t)s0 * (DIN / 4) + t];
        acc.x = fmaf(v0.x, c0, acc.x); acc.y = fmaf(v0.y, c0, acc.y);
        acc.z = fmaf(v0.z, c0, acc.z); acc.w = fmaf(v0.w, c0, acc.w);
    }
    float sd = g_rs_in0[row];
    acc.x *= sd; acc.y *= sd; acc.z *= sd; acc.w *= sd;
    ((float4*)g_agg0)[(size_t)row * (DIN / 4) + t] = acc;
}

// ---------------- layer-1 aggregation ----------------
__global__ void __launch_bounds__(256) aggregate1_kernel() {
    int row = blockIdx.x;
    int t = threadIdx.x;
    if (t >= DHID / 4) return;
    int beg = g_off1[row], end = g_off1[row + 1];
    const float4* h4 = (const float4*)g_h1s;
    float4 acc = make_float4(0.f, 0.f, 0.f, 0.f);
    for (int e = beg; e < end; e++) {
        int s = g_srcs1[e];
        float4 v = h4[(size_t)s * (DHID / 4) + t];
        acc.x += v.x; acc.y += v.y; acc.z += v.z; acc.w += v.w;
    }
    float sd = g_rs_in1[row];
    acc.x *= sd; acc.y *= sd; acc.z *= sd; acc.w *= sd;
    ((float4*)g_agg1)[(size_t)row * (DHID / 4) + t] = acc;
}

// ---------------- tf32 tensor-core GEMM: C = epi(A @ B + bias) ----------------
// LAYER==1: A=g_agg0 [10000,256],  B=W1 [256,1000],  epi: (+b1)*rs_out1[row] -> g_h1s
// LAYER==2: A=g_agg1 [2048,1000],  B=W2 [1000,5000], epi: sigmoid(+b2)       -> d_out
// Block: 256 threads = 8 warps (2m x 4n), tile 128x128, BK=32.
// Warp tile 64x32 = 4x4 m16n8k8 fragments.
template <int LAYER>
__global__ void __launch_bounds__(256) mma_gemm_kernel(const float* __restrict__ B,
                                                       const float* __restrict__ bias,
                                                       float* __restrict__ Cout) {
    constexpr int M = (LAYER == 1) ? NN1 : NN2;
    constexpr int N = (LAYER == 1) ? DHID : NCLS;
    constexpr int K = (LAYER == 1) ? DIN : DHID;
    constexpr int BM = 128, BN = 128, BK = 32;
    constexpr int AS = BK + 4;    // 36: fragment LDS conflict-free
    constexpr int BS = BN + 8;    // 136: fragment LDS conflict-free

    const float* __restrict__ A = (LAYER == 1) ? g_agg0 : g_agg1;
    float* __restrict__ C = (LAYER == 1) ? g_h1s : Cout;

    __shared__ uint32_t As[BM][AS];   // [m][k] tf32 bits
    __shared__ uint32_t Bs[BK][BS];   // [k][n] tf32 bits

    int tid = threadIdx.x;
    int lane = tid & 31;
    int wid = tid >> 5;
    int wm = (wid >> 2) * 64;   // warp m-offset in tile
    int wn = (wid & 3) * 32;    // warp n-offset in tile
    int m0 = blockIdx.y * BM, n0 = blockIdx.x * BN;

    float acc[4][4][4];
#pragma unroll
    for (int mi = 0; mi < 4; mi++)
#pragma unroll
        for (int nj = 0; nj < 4; nj++)
#pragma unroll
            for (int q = 0; q < 4; q++) acc[mi][nj][q] = 0.f;

    // A staging: thread -> row = (tid>>3) + i*32, f4col = tid&7   (coalesced 128B/4rows)
    int a_row = tid >> 3;
    int a_c4 = tid & 7;
    // B staging: thread -> krow = (tid>>5) + i*8, f4col = tid&31  (coalesced 128B/row)
    int b_kr = tid >> 5;
    int b_c4 = tid & 31;

    for (int k0 = 0; k0 < K; k0 += BK) {
        // ---- stage A tile ----
#pragma unroll
        for (int i = 0; i < 4; i++) {
            int row = a_row + i * 32;
            int gm = m0 + row;
            int gk = k0 + a_c4 * 4;
            float4 v = make_float4(0.f, 0.f, 0.f, 0.f);
            if (gm < M && gk < K)    // K%4==0 always, so full float4 valid when gk<K
                v = *(const float4*)&A[(size_t)gm * K + gk];
            uint4 u;
            u.x = f2tf(v.x); u.y = f2tf(v.y); u.z = f2tf(v.z); u.w = f2tf(v.w);
            *(uint4*)&As[row][a_c4 * 4] = u;
        }
        // ---- stage B tile ----
#pragma unroll
        for (int i = 0; i < 4; i++) {
            int kr = b_kr + i * 8;
            int gk = k0 + kr;
            int gn = n0 + b_c4 * 4;
            float4 v = make_float4(0.f, 0.f, 0.f, 0.f);
            if (gk < K) {
                if (gn + 3 < N) {
                    v = *(const float4*)&B[(size_t)gk * N + gn];
                } else {
                    const float* brow = &B[(size_t)gk * N];
                    float tmp[4] = {0.f, 0.f, 0.f, 0.f};
#pragma unroll
                    for (int j = 0; j < 4; j++)
                        if (gn + j < N) tmp[j] = brow[gn + j];
                    v = make_float4(tmp[0], tmp[1], tmp[2], tmp[3]);
                }
            }
            uint4 u;
            u.x = f2tf(v.x); u.y = f2tf(v.y); u.z = f2tf(v.z); u.w = f2tf(v.w);
            *(uint4*)&Bs[kr][b_c4 * 4] = u;
        }
        __syncthreads();

        // ---- compute: 4 k-steps of 8 ----
        int ar = lane >> 2, ac = lane & 3;
#pragma unroll
        for (int ks = 0; ks < 4; ks++) {
            int kb = ks * 8;
            uint32_t af[4][4];
            uint32_t bf[4][2];
#pragma unroll
            for (int mi = 0; mi < 4; mi++) {
                int r = wm + mi * 16 + ar;
                af[mi][0] = As[r][kb + ac];
                af[mi][1] = As[r + 8][kb + ac];
                af[mi][2] = As[r][kb + ac + 4];
                af[mi][3] = As[r + 8][kb + ac + 4];
            }
#pragma unroll
            for (int nj = 0; nj < 4; nj++) {
                int c = wn + nj * 8 + ar;
                bf[nj][0] = Bs[kb + ac][c];
                bf[nj][1] = Bs[kb + ac + 4][c];
            }
#pragma unroll
            for (int mi = 0; mi < 4; mi++)
#pragma unroll
                for (int nj = 0; nj < 4; nj++)
                    mma_tf32(acc[mi][nj], af[mi], bf[nj]);
        }
        __syncthreads();
    }

    // ---- epilogue ----
    int er = lane >> 2;           // fragment row base
    int ec = (lane & 3) * 2;      // fragment col base
#pragma unroll
    for (int mi = 0; mi < 4; mi++) {
#pragma unroll
        for (int half = 0; half < 2; half++) {
            int gm = m0 + wm + mi * 16 + er + half * 8;
            if (gm >= M) continue;
            float rs = (LAYER == 1) ? g_rs_out1[gm] : 1.f;
#pragma unroll
            for (int nj = 0; nj < 4; nj++) {
                int gn = n0 + wn + nj * 8 + ec;
                if (gn >= N) continue;   // N even, so gn+1 < N too
                float v0 = acc[mi][nj][half * 2 + 0] + bias[gn];
                float v1 = acc[mi][nj][half * 2 + 1] + bias[gn + 1];
                if (LAYER == 1) {
                    v0 *= rs; v1 *= rs;
                } else {
                    v0 = 1.f / (1.f + __expf(-v0));
                    v1 = 1.f / (1.f + __expf(-v1));
                }
                *(float2*)&C[(size_t)gm * N + gn] = make_float2(v0, v1);
            }
        }
    }
}

// ---------------- launch ----------------
extern "C" void kernel_launch(void* const* d_in, const int* in_sizes, int n_in,
                              void* d_out, int out_size) {
    const float* x  = (const float*)d_in[0];
    const float* W1 = (const float*)d_in[1];
    const float* b1 = (const float*)d_in[2];
    const float* W2 = (const float*)d_in[3];
    const float* b2 = (const float*)d_in[4];
    const int* e0_src = (const int*)d_in[5];
    const int* e0_dst = (const int*)d_in[6];
    const int* e1_src = (const int*)d_in[7];
    const int* e1_dst = (const int*)d_in[8];
    float* out = (float*)d_out;

    int E0 = in_sizes[5];
    int E1 = in_sizes[7];

    zero_counts_kernel<<<(NN0 + 255) / 256, 256>>>();
    degree_kernel<<<1024, 256>>>(e0_src, e0_dst, e1_src, e1_dst, E0, E1);
    rsqrt_kernel<<<(NN0 + 255) / 256, 256>>>();
    scan0_kernel<<<1, 1024>>>();
    scan1_kernel<<<1, 1024>>>();
    scatter0_kernel<<<1024, 256>>>(e0_src, e0_dst, E0);
    scatter1_kernel<<<512, 256>>>(e1_src, e1_dst, E1);

    aggregate0_kernel<<<NN1, 64>>>(x);

    {
        dim3 grid((DHID + 127) / 128, (NN1 + 127) / 128);
        mma_gemm_kernel<1><<<grid, 256>>>(W1, b1, nullptr);
    }

    aggregate1_kernel<<<NN2, 256>>>();

    {
        dim3 grid((NCLS + 127) / 128, (NN2 + 127) / 128);
        mma_gemm_kernel<2><<<grid, 256>>>(W2, b2, out);
    }
}

// round 4
// speedup vs baseline: 3.7512x; 1.6926x over previous
#include <cuda_runtime.h>
#include <cuda_fp16.h>
#include <cstdint>

// Problem constants (fixed shapes from reference setup_inputs)
#define NN0 50000
#define NN1 10000
#define NN2 2048
#define DIN 256
#define DHID 1000
#define NCLS 5000
#define EE0 500000
#define EE1 100000
#define KP2 1024   // K of GEMM2 padded to 1024 (zero fill)

// ---------------- device scratch (static, allocation-free) ----------------
__device__ int    g_cnt_out0[NN0];
__device__ int    g_cnt_in0[NN1];
__device__ int    g_cnt_out1[NN1];
__device__ int    g_cnt_in1[NN2];
__device__ float  g_rs_out0[NN0];
__device__ float  g_rs_in0[NN1];
__device__ float  g_rs_out1[NN1];
__device__ float  g_rs_in1[NN2];
__device__ int    g_off0[NN1 + 1];
__device__ int    g_cur0[NN1];
__device__ int    g_off1[NN2 + 1];
__device__ int    g_cur1[NN2];
__device__ int    g_srcs0[EE0];
__device__ int    g_srcs1[EE1];
__device__ __half g_xh[(size_t)NN0 * DIN];       // 25.6 MB  x in fp16
__device__ __half g_agg0h[(size_t)NN1 * DIN];    // 5.1 MB   layer0 aggregate (fp16)
__device__ __half g_w1t[(size_t)DHID * DIN];     // 0.5 MB   W1^T [n][k] fp16
__device__ __half g_h1h[(size_t)NN1 * DHID];     // 20 MB    h1 (src-normalized, fp16)
__device__ __half g_agg1h[(size_t)NN2 * KP2];    // 4.2 MB   layer1 aggregate (fp16, k-padded)
__device__ __half g_w2t[(size_t)NCLS * KP2];     // 10.2 MB  W2^T [n][k] fp16 (k-padded)

// ---------------- helpers ----------------
__device__ __forceinline__ void cp_async16(void* smem_dst, const void* gsrc, bool pred) {
    uint32_t saddr = (uint32_t)__cvta_generic_to_shared(smem_dst);
    int sz = pred ? 16 : 0;
    asm volatile("cp.async.cg.shared.global [%0], [%1], 16, %2;\n"
                 :: "r"(saddr), "l"(gsrc), "r"(sz));
}
__device__ __forceinline__ void cp_commit() { asm volatile("cp.async.commit_group;\n"); }
template <int NMAX>
__device__ __forceinline__ void cp_wait() { asm volatile("cp.async.wait_group %0;\n" :: "n"(NMAX)); }

__device__ __forceinline__ void mma_f16(float* d, const uint32_t* a, const uint32_t* b) {
    asm volatile(
        "mma.sync.aligned.m16n8k16.row.col.f32.f16.f16.f32 "
        "{%0,%1,%2,%3}, {%4,%5,%6,%7}, {%8,%9}, {%0,%1,%2,%3};\n"
        : "+f"(d[0]), "+f"(d[1]), "+f"(d[2]), "+f"(d[3])
        : "r"(a[0]), "r"(a[1]), "r"(a[2]), "r"(a[3]), "r"(b[0]), "r"(b[1]));
}

// ---------------- setup kernels ----------------
__global__ void zero_counts_kernel() {
    int i = blockIdx.x * blockDim.x + threadIdx.x;
    int stride = gridDim.x * blockDim.x;
    for (int j = i; j < NN0; j += stride) g_cnt_out0[j] = 0;
    for (int j = i; j < NN1; j += stride) { g_cnt_in0[j] = 0; g_cnt_out1[j] = 0; }
    for (int j = i; j < NN2; j += stride) g_cnt_in1[j] = 0;
}

__global__ void degree_kernel(const int* __restrict__ s0, const int* __restrict__ d0,
                              const int* __restrict__ s1, const int* __restrict__ d1,
                              int E0, int E1) {
    int i = blockIdx.x * blockDim.x + threadIdx.x;
    int stride = gridDim.x * blockDim.x;
    for (int j = i; j < E0; j += stride) {
        atomicAdd(&g_cnt_out0[s0[j]], 1);
        atomicAdd(&g_cnt_in0[d0[j]], 1);
        if (j < E1) {
            atomicAdd(&g_cnt_out1[s1[j]], 1);
            atomicAdd(&g_cnt_in1[d1[j]], 1);
        }
    }
}

__global__ void rsqrt_kernel() {
    int i = blockIdx.x * blockDim.x + threadIdx.x;
    int stride = gridDim.x * blockDim.x;
    for (int j = i; j < NN0; j += stride)
        g_rs_out0[j] = rsqrtf((float)max(g_cnt_out0[j], 1));
    for (int j = i; j < NN1; j += stride) {
        g_rs_in0[j]  = rsqrtf((float)max(g_cnt_in0[j], 1));
        g_rs_out1[j] = rsqrtf((float)max(g_cnt_out1[j], 1));
    }
    for (int j = i; j < NN2; j += stride)
        g_rs_in1[j]  = rsqrtf((float)max(g_cnt_in1[j], 1));
}

// hierarchical shuffle-based exclusive scan: 1024 threads
__device__ __forceinline__ void scan_impl(const int* cnt, int* off, int* cur, int NB) {
    __shared__ int wsum[32];
    int t = threadIdx.x, lane = t & 31, w = t >> 5;
    int IPT = (NB + 1023) / 1024;
    int base = t * IPT;
    int loc[10];
    int s = 0;
    for (int i = 0; i < IPT; i++) {
        int b = base + i;
        int v = (b < NB) ? cnt[b] : 0;
        loc[i] = s;
        s += v;
    }
    int x = s;
    for (int d = 1; d < 32; d <<= 1) {
        int y = __shfl_up_sync(0xffffffffu, x, d);
        if (lane >= d) x += y;
    }
    if (lane == 31) wsum[w] = x;
    __syncthreads();
    if (w == 0) {
        int y = wsum[lane];
        int z = y;
        for (int d = 1; d < 32; d <<= 1) {
            int u = __shfl_up_sync(0xffffffffu, z, d);
            if (lane >= d) z += u;
        }
        wsum[lane] = z - y;
    }
    __syncthreads();
    int excl = (x - s) + wsum[w];
    for (int i = 0; i < IPT; i++) {
        int b = base + i;
        if (b < NB) {
            int o = excl + loc[i];
            off[b] = o;
            cur[b] = o;
        }
    }
    if (t == 1023) off[NB] = excl + s;
}

__global__ void scans_kernel() {
    if (blockIdx.x == 0) scan_impl(g_cnt_in0, g_off0, g_cur0, NN1);
    else                 scan_impl(g_cnt_in1, g_off1, g_cur1, NN2);
}

__global__ void scatters_kernel(const int* __restrict__ s0, const int* __restrict__ d0,
                                const int* __restrict__ s1, const int* __restrict__ d1,
                                int E0, int E1) {
    if (blockIdx.x < 1024) {
        int i = blockIdx.x * blockDim.x + threadIdx.x;
        int stride = 1024 * blockDim.x;
        for (int j = i; j < E0; j += stride) {
            int d = d0[j];
            int p = atomicAdd(&g_cur0[d], 1);
            g_srcs0[p] = s0[j];
        }
    } else {
        int i = (blockIdx.x - 1024) * blockDim.x + threadIdx.x;
        int stride = 256 * blockDim.x;
        for (int j = i; j < E1; j += stride) {
            int d = d1[j];
            int p = atomicAdd(&g_cur1[d], 1);
            g_srcs1[p] = s1[j];
        }
    }
}

// ---------------- conversions ----------------
__global__ void convert_x_kernel(const float* __restrict__ x) {
    int i = blockIdx.x * blockDim.x + threadIdx.x;
    int n4 = NN0 * DIN / 4;
    int stride = gridDim.x * blockDim.x;
    for (; i < n4; i += stride) {
        float4 v = ((const float4*)x)[i];
        __half2 h0 = __floats2half2_rn(v.x, v.y);
        __half2 h1 = __floats2half2_rn(v.z, v.w);
        uint2 u;
        u.x = *(uint32_t*)&h0;
        u.y = *(uint32_t*)&h1;
        ((uint2*)g_xh)[i] = u;
    }
}

// transpose W [K][N] fp32 -> Wt [N][KPad] fp16 (zero-pad k in [K,KPad))
__global__ void transpose_w_kernel(const float* __restrict__ W, __half* __restrict__ Wt,
                                   int K, int N, int KPad) {
    __shared__ float tile[32][33];
    int kb = blockIdx.y * 32, nb = blockIdx.x * 32;
    int tx = threadIdx.x, ty = threadIdx.y;  // (32, 8)
    for (int i = 0; i < 32; i += 8) {
        int gk = kb + ty + i, gn = nb + tx;
        float v = 0.f;
        if (gk < K && gn < N) v = W[(size_t)gk * N + gn];
        tile[ty + i][tx] = v;
    }
    __syncthreads();
    for (int i = 0; i < 32; i += 8) {
        int gn = nb + ty + i, gk = kb + tx;
        if (gn < N && gk < KPad)
            Wt[(size_t)gn * KPad + gk] = __float2half(tile[tx][ty + i]);
    }
}

// ---------------- layer-0 aggregation (fp16 gather, fp32 accum, fp16 out) ----------------
__global__ void __launch_bounds__(64) aggregate0_kernel() {
    int row = blockIdx.x;
    int t = threadIdx.x;
    int beg = g_off0[row], end = g_off0[row + 1];
    const uint2* x2 = (const uint2*)g_xh;  // 4 halves per uint2, row stride 64
    float4 acc = make_float4(0.f, 0.f, 0.f, 0.f);
    for (int e = beg; e < end; e++) {
        int s = g_srcs0[e];
        float c = g_rs_out0[s];
        uint2 u = x2[(size_t)s * (DIN / 4) + t];
        __half2 h0 = *(__half2*)&u.x;
        __half2 h1 = *(__half2*)&u.y;
        float2 f0 = __half22float2(h0);
        float2 f1 = __half22float2(h1);
        acc.x = fmaf(f0.x, c, acc.x); acc.y = fmaf(f0.y, c, acc.y);
        acc.z = fmaf(f1.x, c, acc.z); acc.w = fmaf(f1.y, c, acc.w);
    }
    float sd = g_rs_in0[row];
    __half2 o0 = __floats2half2_rn(acc.x * sd, acc.y * sd);
    __half2 o1 = __floats2half2_rn(acc.z * sd, acc.w * sd);
    uint2 ou;
    ou.x = *(uint32_t*)&o0;
    ou.y = *(uint32_t*)&o1;
    ((uint2*)g_agg0h)[(size_t)row * (DIN / 4) + t] = ou;
}

// ---------------- layer-1 aggregation (fp16 gather of h1, fp32 accum, fp16 out k-padded) ----
__global__ void __launch_bounds__(256) aggregate1_kernel() {
    int row = blockIdx.x;
    int t = threadIdx.x;
    const uint2* h2 = (const uint2*)g_h1h;  // row stride 250 uint2
    uint2 ou;
    if (t < DHID / 4) {
        int beg = g_off1[row], end = g_off1[row + 1];
        float4 acc = make_float4(0.f, 0.f, 0.f, 0.f);
        for (int e = beg; e < end; e++) {
            int s = g_srcs1[e];
            uint2 u = h2[(size_t)s * (DHID / 4) + t];
            __half2 h0 = *(__half2*)&u.x;
            __half2 h1 = *(__half2*)&u.y;
            float2 f0 = __half22float2(h0);
            float2 f1 = __half22float2(h1);
            acc.x += f0.x; acc.y += f0.y; acc.z += f1.x; acc.w += f1.y;
        }
        float sd = g_rs_in1[row];
        __half2 o0 = __floats2half2_rn(acc.x * sd, acc.y * sd);
        __half2 o1 = __floats2half2_rn(acc.z * sd, acc.w * sd);
        ou.x = *(uint32_t*)&o0;
        ou.y = *(uint32_t*)&o1;
    } else {
        ou.x = 0u; ou.y = 0u;  // zero-pad k in [1000,1024)
    }
    ((uint2*)g_agg1h)[(size_t)row * (KP2 / 4) + t] = ou;
}

// ---------------- fp16 tensor-core GEMM, cp.async double-buffered ----------------
// LAYER==1: A=g_agg0h [10000,256], B=g_w1t [1000,256],  epi:(+b1)*rs_out1 -> g_h1h (fp16)
// LAYER==2: A=g_agg1h [2048,1024], B=g_w2t [5000,1024], epi:sigmoid(+b2)  -> d_out (fp32)
// Block 256 thr = 8 warps (2m x 4n); tile 128x128; BK=32 halves; warp tile 64x32.
#define BKP 40  // 32 + 8-half pad -> conflict-free fragment LDS (80B = 20-word row stride)

__device__ __forceinline__ void stage_tile(__half (*S)[BKP], const __half* __restrict__ src,
                                           int rowbase, int rowlim, int k0, int kstride, int tid) {
    int r = tid >> 1;
    int c = (tid & 1) * 16;
    bool p = (rowbase + r) < rowlim;
    size_t grow = p ? (size_t)(rowbase + r) : 0;
    const __half* g = src + grow * kstride + k0 + c;
    cp_async16(&S[r][c], g, p);
    cp_async16(&S[r][c + 8], g + 8, p);
}

template <int LAYER>
__global__ void __launch_bounds__(256) mma_gemm_kernel(const float* __restrict__ bias,
                                                       float* __restrict__ Cout) {
    constexpr int M = (LAYER == 1) ? NN1 : NN2;
    constexpr int N = (LAYER == 1) ? DHID : NCLS;
    constexpr int K = (LAYER == 1) ? DIN : KP2;   // padded K (mult of 32)
    constexpr int NI = K / 32;

    const __half* __restrict__ Ah = (LAYER == 1) ? g_agg0h : g_agg1h;
    const __half* __restrict__ Bh = (LAYER == 1) ? g_w1t : g_w2t;

    __shared__ __align__(16) __half As[2][128][BKP];
    __shared__ __align__(16) __half Bs[2][128][BKP];

    int tid = threadIdx.x;
    int lane = tid & 31;
    int wid = tid >> 5;
    int wm = (wid >> 2) * 64;
    int wn = (wid & 3) * 32;
    int m0 = blockIdx.y * 128, n0 = blockIdx.x * 128;

    float acc[4][4][4];
#pragma unroll
    for (int mi = 0; mi < 4; mi++)
#pragma unroll
        for (int nj = 0; nj < 4; nj++)
#pragma unroll
            for (int q = 0; q < 4; q++) acc[mi][nj][q] = 0.f;

    stage_tile(As[0], Ah, m0, M, 0, K, tid);
    stage_tile(Bs[0], Bh, n0, N, 0, K, tid);
    cp_commit();
    stage_tile(As[1], Ah, m0, M, 32, K, tid);
    stage_tile(Bs[1], Bh, n0, N, 32, K, tid);
    cp_commit();

    int ar = lane >> 2;
    int aq = (lane & 3) * 2;

    for (int i = 0; i < NI; i++) {
        cp_wait<1>();
        __syncthreads();
        const __half (*Ab)[BKP] = As[i & 1];
        const __half (*Bb)[BKP] = Bs[i & 1];
#pragma unroll
        for (int ks = 0; ks < 2; ks++) {
            int kb = ks * 16 + aq;
            uint32_t af[4][4];
            uint32_t bf[4][2];
#pragma unroll
            for (int mi = 0; mi < 4; mi++) {
                int r = wm + mi * 16 + ar;
                af[mi][0] = *(const uint32_t*)&Ab[r][kb];
                af[mi][1] = *(const uint32_t*)&Ab[r + 8][kb];
                af[mi][2] = *(const uint32_t*)&Ab[r][kb + 8];
                af[mi][3] = *(const uint32_t*)&Ab[r + 8][kb + 8];
            }
#pragma unroll
            for (int nj = 0; nj < 4; nj++) {
                int c = wn + nj * 8 + ar;
                bf[nj][0] = *(const uint32_t*)&Bb[c][kb];
                bf[nj][1] = *(const uint32_t*)&Bb[c][kb + 8];
            }
#pragma unroll
            for (int mi = 0; mi < 4; mi++)
#pragma unroll
                for (int nj = 0; nj < 4; nj++)
                    mma_f16(acc[mi][nj], af[mi], bf[nj]);
        }
        __syncthreads();
        if (i + 2 < NI) {
            stage_tile(As[i & 1], Ah, m0, M, (i + 2) * 32, K, tid);
            stage_tile(Bs[i & 1], Bh, n0, N, (i + 2) * 32, K, tid);
        }
        cp_commit();
    }

    // ---- epilogue ----
    int er = lane >> 2;
    int ec = (lane & 3) * 2;
#pragma unroll
    for (int mi = 0; mi < 4; mi++) {
#pragma unroll
        for (int half_ = 0; half_ < 2; half_++) {
            int gm = m0 + wm + mi * 16 + er + half_ * 8;
            if (gm >= M) continue;
            float rs = (LAYER == 1) ? g_rs_out1[gm] : 1.f;
#pragma unroll
            for (int nj = 0; nj < 4; nj++) {
                int gn = n0 + wn + nj * 8 + ec;
                if (gn >= N) continue;  // N even => gn+1 < N too
                float v0 = acc[mi][nj][half_ * 2 + 0] + bias[gn];
                float v1 = acc[mi][nj][half_ * 2 + 1] + bias[gn + 1];
                if (LAYER == 1) {
                    v0 *= rs; v1 *= rs;
                    __half2 h = __floats2half2_rn(v0, v1);
                    *(uint32_t*)&g_h1h[(size_t)gm * DHID + gn] = *(uint32_t*)&h;
                } else {
                    v0 = 1.f / (1.f + __expf(-v0));
                    v1 = 1.f / (1.f + __expf(-v1));
                    *(float2*)&Cout[(size_t)gm * N + gn] = make_float2(v0, v1);
                }
            }
        }
    }
}

// ---------------- launch ----------------
extern "C" void kernel_launch(void* const* d_in, const int* in_sizes, int n_in,
                              void* d_out, int out_size) {
    const float* x  = (const float*)d_in[0];
    const float* W1 = (const float*)d_in[1];
    const float* b1 = (const float*)d_in[2];
    const float* W2 = (const float*)d_in[3];
    const float* b2 = (const float*)d_in[4];
    const int* e0_src = (const int*)d_in[5];
    const int* e0_dst = (const int*)d_in[6];
    const int* e1_src = (const int*)d_in[7];
    const int* e1_dst = (const int*)d_in[8];
    float* out = (float*)d_out;

    int E0 = in_sizes[5];
    int E1 = in_sizes[7];

    __half* p_w1t;
    __half* p_w2t;
    cudaGetSymbolAddress((void**)&p_w1t, g_w1t);
    cudaGetSymbolAddress((void**)&p_w2t, g_w2t);

    zero_counts_kernel<<<(NN0 + 255) / 256, 256>>>();
    degree_kernel<<<1024, 256>>>(e0_src, e0_dst, e1_src, e1_dst, E0, E1);
    rsqrt_kernel<<<(NN0 + 255) / 256, 256>>>();
    scans_kernel<<<2, 1024>>>();
    scatters_kernel<<<1280, 256>>>(e0_src, e0_dst, e1_src, e1_dst, E0, E1);

    convert_x_kernel<<<400, 256>>>(x);
    {
        dim3 grid((DHID + 31) / 32, DIN / 32);
        transpose_w_kernel<<<grid, dim3(32, 8)>>>(W1, p_w1t, DIN, DHID, DIN);
    }
    {
        dim3 grid((NCLS + 31) / 32, KP2 / 32);
        transpose_w_kernel<<<grid, dim3(32, 8)>>>(W2, p_w2t, DHID, NCLS, KP2);
    }

    aggregate0_kernel<<<NN1, 64>>>();

    {
        dim3 grid((DHID + 127) / 128, (NN1 + 127) / 128);
        mma_gemm_kernel<1><<<grid, 256>>>(b1, nullptr);
    }

    aggregate1_kernel<<<NN2, 256>>>();

    {
        dim3 grid((NCLS + 127) / 128, (NN2 + 127) / 128);
        mma_gemm_kernel<2><<<grid, 256>>>(b2, out);
    }
}